// round 1
// baseline (speedup 1.0000x reference)
#include <cuda_runtime.h>
#include <math.h>

// Problem constants (fixed by the reference): B=8, C=512, N=4096, G=8
#define BB 8
#define CC 512
#define NN 4096
#define GG 8
#define CG (CC / GG)            // 64 channels per group
#define GROUP_ELEMS (CG * NN)   // 262144 floats per (b,g) group
#define SLABS 8
#define SLAB_ELEMS (GROUP_ELEMS / SLABS)   // 32768 floats
#define SLAB_V4 (SLAB_ELEMS / 4)           // 8192 float4

// ---------------------------------------------------------------------------
// Scratch (static device globals — no allocation at runtime)
// ---------------------------------------------------------------------------
__device__ float  g_h[(size_t)BB * CC * NN];          // 64 MB  groupnorm output
__device__ float  g_qkv[(size_t)BB * 3 * CC * NN];    // 192 MB qkv (k softmaxed in place)
__device__ float  g_ctx[(size_t)BB * CC * CC];        // 8 MB   k @ v^T
__device__ float  g_att[(size_t)BB * CC * NN];        // 64 MB  attention output
__device__ float2 g_part[BB * GG * SLABS];            // groupnorm partial sums

// ---------------------------------------------------------------------------
// GroupNorm pass 1: partial sum / sumsq per (b,g,slab)
// grid (B*G, SLABS), 256 threads
// ---------------------------------------------------------------------------
__global__ __launch_bounds__(256) void gn_partial_kernel(const float* __restrict__ x,
                                                         float2* __restrict__ part)
{
    int bg = blockIdx.x, slab = blockIdx.y;
    const float4* p = (const float4*)(x + (size_t)bg * GROUP_ELEMS + (size_t)slab * SLAB_ELEMS);
    float s1 = 0.f, s2 = 0.f;
    for (int i = threadIdx.x; i < SLAB_V4; i += 256) {
        float4 v = p[i];
        s1 += (v.x + v.y) + (v.z + v.w);
        s2 += (v.x * v.x + v.y * v.y) + (v.z * v.z + v.w * v.w);
    }
    #pragma unroll
    for (int o = 16; o > 0; o >>= 1) {
        s1 += __shfl_xor_sync(0xffffffffu, s1, o);
        s2 += __shfl_xor_sync(0xffffffffu, s2, o);
    }
    __shared__ float2 red[8];
    if ((threadIdx.x & 31) == 0) red[threadIdx.x >> 5] = make_float2(s1, s2);
    __syncthreads();
    if (threadIdx.x == 0) {
        float S1 = 0.f, S2 = 0.f;
        #pragma unroll
        for (int i = 0; i < 8; i++) { S1 += red[i].x; S2 += red[i].y; }
        part[bg * SLABS + slab] = make_float2(S1, S2);
    }
}

// ---------------------------------------------------------------------------
// GroupNorm pass 2: normalize + affine -> g_h
// grid (B*G, SLABS), 256 threads
// ---------------------------------------------------------------------------
__global__ __launch_bounds__(256) void gn_apply_kernel(const float* __restrict__ x,
                                                       const float* __restrict__ scale,
                                                       const float* __restrict__ bias,
                                                       const float2* __restrict__ part,
                                                       float* __restrict__ h)
{
    int bg = blockIdx.x, slab = blockIdx.y;
    float S1 = 0.f, S2 = 0.f;
    #pragma unroll
    for (int i = 0; i < SLABS; i++) {
        float2 p = part[bg * SLABS + i];
        S1 += p.x; S2 += p.y;
    }
    const float inv_cnt = 1.f / (float)GROUP_ELEMS;
    float mean = S1 * inv_cnt;
    float var  = S2 * inv_cnt - mean * mean;
    float rstd = rsqrtf(var + 1e-6f);

    int g = bg & (GG - 1);
    size_t base = (size_t)bg * GROUP_ELEMS + (size_t)slab * SLAB_ELEMS;
    const float4* px = (const float4*)(x + base);
    float4* ph = (float4*)(h + base);
    for (int i = threadIdx.x; i < SLAB_V4; i += 256) {
        int e = slab * SLAB_ELEMS + i * 4;        // offset within group region
        int c = g * CG + (e >> 12);               // e / 4096 -> channel within group
        float sc = scale[c] * rstd;
        float bi = bias[c] - mean * sc;
        float4 v = px[i];
        v.x = v.x * sc + bi;
        v.y = v.y * sc + bi;
        v.z = v.z * sc + bi;
        v.w = v.w * sc + bi;
        ph[i] = v;
    }
}

// ---------------------------------------------------------------------------
// Row softmax over tokens for the k slice of qkv (in place).
// grid (B*C), 256 threads; each block handles one 4096-float row.
// ---------------------------------------------------------------------------
__global__ __launch_bounds__(256) void softmax_kernel(float* __restrict__ qkv)
{
    int rid = blockIdx.x;
    int b = rid >> 9, d = rid & (CC - 1);
    float4* r4 = (float4*)(qkv + (size_t)b * 3 * CC * NN + (size_t)(CC + d) * NN);
    int tid = threadIdx.x;

    float4 v[4];
    float mx = -INFINITY;
    #pragma unroll
    for (int i = 0; i < 4; i++) {
        v[i] = r4[tid + i * 256];
        mx = fmaxf(mx, fmaxf(fmaxf(v[i].x, v[i].y), fmaxf(v[i].z, v[i].w)));
    }
    #pragma unroll
    for (int o = 16; o > 0; o >>= 1) mx = fmaxf(mx, __shfl_xor_sync(0xffffffffu, mx, o));
    __shared__ float red[8];
    if ((tid & 31) == 0) red[tid >> 5] = mx;
    __syncthreads();
    mx = red[0];
    #pragma unroll
    for (int i = 1; i < 8; i++) mx = fmaxf(mx, red[i]);

    float sum = 0.f;
    #pragma unroll
    for (int i = 0; i < 4; i++) {
        v[i].x = expf(v[i].x - mx);
        v[i].y = expf(v[i].y - mx);
        v[i].z = expf(v[i].z - mx);
        v[i].w = expf(v[i].w - mx);
        sum += (v[i].x + v[i].y) + (v[i].z + v[i].w);
    }
    #pragma unroll
    for (int o = 16; o > 0; o >>= 1) sum += __shfl_xor_sync(0xffffffffu, sum, o);
    __syncthreads();
    if ((tid & 31) == 0) red[tid >> 5] = sum;
    __syncthreads();
    sum = 0.f;
    #pragma unroll
    for (int i = 0; i < 8; i++) sum += red[i];
    float inv = 1.f / sum;
    #pragma unroll
    for (int i = 0; i < 4; i++) {
        v[i].x *= inv; v[i].y *= inv; v[i].z *= inv; v[i].w *= inv;
        r4[tid + i * 256] = v[i];
    }
}

// ---------------------------------------------------------------------------
// Batched SGEMM: C[b] = scale * op(A[b]) @ op(B[b]) + bias + resid
//   TA=false: A_eff[m,k] = A[m*K + k]     TA=true:  A_eff[m,k] = A[k*M + m]
//   TB=false: B_eff[k,n] = B[k*N + n]     TB=true:  B_eff[k,n] = B[n*K + k]
// Tiles: 128x128x16, 256 threads, 8x8 per thread. All dims divide tiles.
// ---------------------------------------------------------------------------
#define BM 128
#define BN 128
#define BK 16

template<bool TA, bool TB>
__global__ __launch_bounds__(256) void gemm_kernel(
    const float* __restrict__ A, long sA,
    const float* __restrict__ B, long sB,
    float* __restrict__ C, long sC,
    int M, int N, int K,
    const float* __restrict__ bias,
    const float* __restrict__ resid, long sR,
    float scale)
{
    __shared__ float As[BK][BM + 4];
    __shared__ float Bs[BK][BN + 4];

    int b = blockIdx.z;
    A += (size_t)b * sA;
    B += (size_t)b * sB;
    C += (size_t)b * sC;

    int m0 = blockIdx.y * BM;
    int n0 = blockIdx.x * BN;
    int tid = threadIdx.x;

    // transpose-load mapping (128 rows x 16 cols, scatter)
    int tr = tid >> 2;            // 0..63 (+64)
    int tc = (tid & 3) * 4;       // 0,4,8,12
    // direct-load mapping (16 rows x 128 cols, float4 rows)
    int dr = tid >> 5;            // 0..7 (+8)
    int dc = (tid & 31) * 4;      // 0..124

    int tm = (tid >> 4) * 8;      // output row offset within tile
    int tn = (tid & 15) * 8;      // output col offset within tile

    float acc[8][8] = {};

    for (int k0 = 0; k0 < K; k0 += BK) {
        if (!TA) {
            #pragma unroll
            for (int rr = 0; rr < 2; rr++) {
                int row = tr + rr * 64;
                float4 v = *(const float4*)(A + (size_t)(m0 + row) * K + k0 + tc);
                As[tc + 0][row] = v.x;
                As[tc + 1][row] = v.y;
                As[tc + 2][row] = v.z;
                As[tc + 3][row] = v.w;
            }
        } else {
            #pragma unroll
            for (int rr = 0; rr < 2; rr++) {
                int row = dr + rr * 8;
                float4 v = *(const float4*)(A + (size_t)(k0 + row) * M + m0 + dc);
                *(float4*)&As[row][dc] = v;
            }
        }
        if (!TB) {
            #pragma unroll
            for (int rr = 0; rr < 2; rr++) {
                int row = dr + rr * 8;
                float4 v = *(const float4*)(B + (size_t)(k0 + row) * N + n0 + dc);
                *(float4*)&Bs[row][dc] = v;
            }
        } else {
            #pragma unroll
            for (int rr = 0; rr < 2; rr++) {
                int row = tr + rr * 64;
                float4 v = *(const float4*)(B + (size_t)(n0 + row) * K + k0 + tc);
                Bs[tc + 0][row] = v.x;
                Bs[tc + 1][row] = v.y;
                Bs[tc + 2][row] = v.z;
                Bs[tc + 3][row] = v.w;
            }
        }
        __syncthreads();

        #pragma unroll
        for (int kk = 0; kk < BK; kk++) {
            float a[8], bb[8];
            *(float4*)(a)      = *(const float4*)&As[kk][tm];
            *(float4*)(a + 4)  = *(const float4*)&As[kk][tm + 4];
            *(float4*)(bb)     = *(const float4*)&Bs[kk][tn];
            *(float4*)(bb + 4) = *(const float4*)&Bs[kk][tn + 4];
            #pragma unroll
            for (int i = 0; i < 8; i++)
                #pragma unroll
                for (int j = 0; j < 8; j++)
                    acc[i][j] = fmaf(a[i], bb[j], acc[i][j]);
        }
        __syncthreads();
    }

    // epilogue: v = acc*scale + bias[row] (+ resid)
    #pragma unroll
    for (int i = 0; i < 8; i++) {
        int row = m0 + tm + i;
        float bia = bias ? bias[row] : 0.f;
        size_t rowbase = (size_t)row * N + n0 + tn;
        #pragma unroll
        for (int jj = 0; jj < 8; jj += 4) {
            float4 v;
            v.x = acc[i][jj + 0] * scale + bia;
            v.y = acc[i][jj + 1] * scale + bia;
            v.z = acc[i][jj + 2] * scale + bia;
            v.w = acc[i][jj + 3] * scale + bia;
            if (resid) {
                float4 r = *(const float4*)(resid + (size_t)b * sR + rowbase + jj);
                v.x += r.x; v.y += r.y; v.z += r.z; v.w += r.w;
            }
            *(float4*)(C + rowbase + jj) = v;
        }
    }
}

// ---------------------------------------------------------------------------
// Launch
// Inputs (metadata order): x, qkv_w, qkv_b, proj_w, proj_b, gn_scale, gn_bias
// ---------------------------------------------------------------------------
extern "C" void kernel_launch(void* const* d_in, const int* in_sizes, int n_in,
                              void* d_out, int out_size)
{
    const float* x        = (const float*)d_in[0];
    const float* qkv_w    = (const float*)d_in[1];
    const float* qkv_b    = (const float*)d_in[2];
    const float* proj_w   = (const float*)d_in[3];
    const float* proj_b   = (const float*)d_in[4];
    const float* gn_scale = (const float*)d_in[5];
    const float* gn_bias  = (const float*)d_in[6];
    float* out = (float*)d_out;

    float *h_, *qkv_, *ctx_, *att_;
    float2* part_;
    cudaGetSymbolAddress((void**)&h_,   g_h);
    cudaGetSymbolAddress((void**)&qkv_, g_qkv);
    cudaGetSymbolAddress((void**)&ctx_, g_ctx);
    cudaGetSymbolAddress((void**)&att_, g_att);
    cudaGetSymbolAddress((void**)&part_, g_part);

    const long sX   = (long)CC * NN;           // per-batch stride of x/h/att/out
    const long sQKV = (long)3 * CC * NN;
    const long sCTX = (long)CC * CC;
    const float qscale = 0.044194173824159216f; // 512^-0.5

    // 1) GroupNorm
    gn_partial_kernel<<<dim3(BB * GG, SLABS), 256>>>(x, part_);
    gn_apply_kernel<<<dim3(BB * GG, SLABS), 256>>>(x, gn_scale, gn_bias, part_, h_);

    // 2) qkv = W @ h + b       [M=1536, N=4096, K=512]
    gemm_kernel<false, false><<<dim3(NN / BN, 3 * CC / BM, BB), 256>>>(
        qkv_w, 0, h_, sX, qkv_, sQKV, 3 * CC, NN, CC,
        qkv_b, nullptr, 0, 1.f);

    // 3) k = softmax(k) over tokens (in place on qkv middle slice)
    softmax_kernel<<<BB * CC, 256>>>(qkv_);

    // 4) ctx[d,e] = sum_n k[d,n] v[e,n]     [M=512, N=512, K=4096]  NT
    gemm_kernel<false, true><<<dim3(CC / BN, CC / BM, BB), 256>>>(
        qkv_ + (size_t)CC * NN, sQKV, qkv_ + (size_t)2 * CC * NN, sQKV,
        ctx_, sCTX, CC, CC, NN,
        nullptr, nullptr, 0, 1.f);

    // 5) att[e,n] = qscale * sum_d ctx[d,e] q[d,n]   [M=512, N=4096, K=512] TN
    gemm_kernel<true, false><<<dim3(NN / BN, CC / BM, BB), 256>>>(
        ctx_, sCTX, qkv_, sQKV, att_, sX, CC, NN, CC,
        nullptr, nullptr, 0, qscale);

    // 6) out = proj_w @ att + proj_b + x   [M=512, N=4096, K=512] NN + residual
    gemm_kernel<false, false><<<dim3(NN / BN, CC / BM, BB), 256>>>(
        proj_w, 0, att_, sX, out, sX, CC, NN, CC,
        proj_b, x, sX, 1.f);
}

// round 2
// speedup vs baseline: 1.0001x; 1.0001x over previous
#include <cuda_runtime.h>
#include <math.h>

// Problem constants (fixed by the reference): B=8, C=512, N=4096, G=8
#define BB 8
#define CC 512
#define NN 4096
#define GG 8
#define CG (CC / GG)            // 64 channels per group
#define GROUP_ELEMS (CG * NN)   // 262144 floats per (b,g) group
#define SLABS 8
#define SLAB_ELEMS (GROUP_ELEMS / SLABS)   // 32768 floats
#define SLAB_V4 (SLAB_ELEMS / 4)           // 8192 float4

// ---------------------------------------------------------------------------
// Scratch (static device globals — no allocation at runtime)
// ---------------------------------------------------------------------------
__device__ float  g_h[(size_t)BB * CC * NN];          // 64 MB  groupnorm output
__device__ float  g_qkv[(size_t)BB * 3 * CC * NN];    // 192 MB qkv (k softmaxed in place)
__device__ float  g_ctx[(size_t)BB * CC * CC];        // 8 MB   k @ v^T
__device__ float  g_att[(size_t)BB * CC * NN];        // 64 MB  attention output
__device__ float2 g_part[BB * GG * SLABS];            // groupnorm partial sums

// ---------------------------------------------------------------------------
// GroupNorm pass 1: partial sum / sumsq per (b,g,slab)
// grid (B*G, SLABS), 256 threads
// ---------------------------------------------------------------------------
__global__ __launch_bounds__(256) void gn_partial_kernel(const float* __restrict__ x,
                                                         float2* __restrict__ part)
{
    int bg = blockIdx.x, slab = blockIdx.y;
    const float4* p = (const float4*)(x + (size_t)bg * GROUP_ELEMS + (size_t)slab * SLAB_ELEMS);
    float s1 = 0.f, s2 = 0.f;
    for (int i = threadIdx.x; i < SLAB_V4; i += 256) {
        float4 v = p[i];
        s1 += (v.x + v.y) + (v.z + v.w);
        s2 += (v.x * v.x + v.y * v.y) + (v.z * v.z + v.w * v.w);
    }
    #pragma unroll
    for (int o = 16; o > 0; o >>= 1) {
        s1 += __shfl_xor_sync(0xffffffffu, s1, o);
        s2 += __shfl_xor_sync(0xffffffffu, s2, o);
    }
    __shared__ float2 red[8];
    if ((threadIdx.x & 31) == 0) red[threadIdx.x >> 5] = make_float2(s1, s2);
    __syncthreads();
    if (threadIdx.x == 0) {
        float S1 = 0.f, S2 = 0.f;
        #pragma unroll
        for (int i = 0; i < 8; i++) { S1 += red[i].x; S2 += red[i].y; }
        part[bg * SLABS + slab] = make_float2(S1, S2);
    }
}

// ---------------------------------------------------------------------------
// GroupNorm pass 2: normalize + affine -> g_h
// grid (B*G, SLABS), 256 threads
// ---------------------------------------------------------------------------
__global__ __launch_bounds__(256) void gn_apply_kernel(const float* __restrict__ x,
                                                       const float* __restrict__ scale,
                                                       const float* __restrict__ bias,
                                                       const float2* __restrict__ part,
                                                       float* __restrict__ h)
{
    int bg = blockIdx.x, slab = blockIdx.y;
    float S1 = 0.f, S2 = 0.f;
    #pragma unroll
    for (int i = 0; i < SLABS; i++) {
        float2 p = part[bg * SLABS + i];
        S1 += p.x; S2 += p.y;
    }
    const float inv_cnt = 1.f / (float)GROUP_ELEMS;
    float mean = S1 * inv_cnt;
    float var  = S2 * inv_cnt - mean * mean;
    float rstd = rsqrtf(var + 1e-6f);

    int g = bg & (GG - 1);
    size_t base = (size_t)bg * GROUP_ELEMS + (size_t)slab * SLAB_ELEMS;
    const float4* px = (const float4*)(x + base);
    float4* ph = (float4*)(h + base);
    for (int i = threadIdx.x; i < SLAB_V4; i += 256) {
        int e = slab * SLAB_ELEMS + i * 4;        // offset within group region
        int c = g * CG + (e >> 12);               // e / 4096 -> channel within group
        float sc = scale[c] * rstd;
        float bi = bias[c] - mean * sc;
        float4 v = px[i];
        v.x = v.x * sc + bi;
        v.y = v.y * sc + bi;
        v.z = v.z * sc + bi;
        v.w = v.w * sc + bi;
        ph[i] = v;
    }
}

// ---------------------------------------------------------------------------
// Row softmax over tokens for the k slice of qkv (in place).
// grid (B*C), 256 threads; each block handles one 4096-float row.
// ---------------------------------------------------------------------------
__global__ __launch_bounds__(256) void softmax_kernel(float* __restrict__ qkv)
{
    int rid = blockIdx.x;
    int b = rid >> 9, d = rid & (CC - 1);
    float4* r4 = (float4*)(qkv + (size_t)b * 3 * CC * NN + (size_t)(CC + d) * NN);
    int tid = threadIdx.x;

    float4 v[4];
    float mx = -INFINITY;
    #pragma unroll
    for (int i = 0; i < 4; i++) {
        v[i] = r4[tid + i * 256];
        mx = fmaxf(mx, fmaxf(fmaxf(v[i].x, v[i].y), fmaxf(v[i].z, v[i].w)));
    }
    #pragma unroll
    for (int o = 16; o > 0; o >>= 1) mx = fmaxf(mx, __shfl_xor_sync(0xffffffffu, mx, o));
    __shared__ float red[8];
    if ((tid & 31) == 0) red[tid >> 5] = mx;
    __syncthreads();
    mx = red[0];
    #pragma unroll
    for (int i = 1; i < 8; i++) mx = fmaxf(mx, red[i]);

    float sum = 0.f;
    #pragma unroll
    for (int i = 0; i < 4; i++) {
        v[i].x = expf(v[i].x - mx);
        v[i].y = expf(v[i].y - mx);
        v[i].z = expf(v[i].z - mx);
        v[i].w = expf(v[i].w - mx);
        sum += (v[i].x + v[i].y) + (v[i].z + v[i].w);
    }
    #pragma unroll
    for (int o = 16; o > 0; o >>= 1) sum += __shfl_xor_sync(0xffffffffu, sum, o);
    __syncthreads();
    if ((tid & 31) == 0) red[tid >> 5] = sum;
    __syncthreads();
    sum = 0.f;
    #pragma unroll
    for (int i = 0; i < 8; i++) sum += red[i];
    float inv = 1.f / sum;
    #pragma unroll
    for (int i = 0; i < 4; i++) {
        v[i].x *= inv; v[i].y *= inv; v[i].z *= inv; v[i].w *= inv;
        r4[tid + i * 256] = v[i];
    }
}

// ---------------------------------------------------------------------------
// Batched SGEMM: C[b] = scale * op(A[b]) @ op(B[b]) + bias + resid
//   TA=false: A_eff[m,k] = A[m*K + k]     TA=true:  A_eff[m,k] = A[k*M + m]
//   TB=false: B_eff[k,n] = B[k*N + n]     TB=true:  B_eff[k,n] = B[n*K + k]
// Tiles: 128x128x16, 256 threads, 8x8 per thread. All dims divide tiles.
// ---------------------------------------------------------------------------
#define BM 128
#define BN 128
#define BK 16

template<bool TA, bool TB>
__global__ __launch_bounds__(256) void gemm_kernel(
    const float* __restrict__ A, long sA,
    const float* __restrict__ B, long sB,
    float* __restrict__ C, long sC,
    int M, int N, int K,
    const float* __restrict__ bias,
    const float* __restrict__ resid, long sR,
    float scale)
{
    __shared__ float As[BK][BM + 4];
    __shared__ float Bs[BK][BN + 4];

    int b = blockIdx.z;
    A += (size_t)b * sA;
    B += (size_t)b * sB;
    C += (size_t)b * sC;

    int m0 = blockIdx.y * BM;
    int n0 = blockIdx.x * BN;
    int tid = threadIdx.x;

    // transpose-load mapping (128 rows x 16 cols, scatter)
    int tr = tid >> 2;            // 0..63 (+64)
    int tc = (tid & 3) * 4;       // 0,4,8,12
    // direct-load mapping (16 rows x 128 cols, float4 rows)
    int dr = tid >> 5;            // 0..7 (+8)
    int dc = (tid & 31) * 4;      // 0..124

    int tm = (tid >> 4) * 8;      // output row offset within tile
    int tn = (tid & 15) * 8;      // output col offset within tile

    float acc[8][8] = {};

    for (int k0 = 0; k0 < K; k0 += BK) {
        if (!TA) {
            #pragma unroll
            for (int rr = 0; rr < 2; rr++) {
                int row = tr + rr * 64;
                float4 v = *(const float4*)(A + (size_t)(m0 + row) * K + k0 + tc);
                As[tc + 0][row] = v.x;
                As[tc + 1][row] = v.y;
                As[tc + 2][row] = v.z;
                As[tc + 3][row] = v.w;
            }
        } else {
            #pragma unroll
            for (int rr = 0; rr < 2; rr++) {
                int row = dr + rr * 8;
                float4 v = *(const float4*)(A + (size_t)(k0 + row) * M + m0 + dc);
                *(float4*)&As[row][dc] = v;
            }
        }
        if (!TB) {
            #pragma unroll
            for (int rr = 0; rr < 2; rr++) {
                int row = dr + rr * 8;
                float4 v = *(const float4*)(B + (size_t)(k0 + row) * N + n0 + dc);
                *(float4*)&Bs[row][dc] = v;
            }
        } else {
            #pragma unroll
            for (int rr = 0; rr < 2; rr++) {
                int row = tr + rr * 64;
                float4 v = *(const float4*)(B + (size_t)(n0 + row) * K + k0 + tc);
                Bs[tc + 0][row] = v.x;
                Bs[tc + 1][row] = v.y;
                Bs[tc + 2][row] = v.z;
                Bs[tc + 3][row] = v.w;
            }
        }
        __syncthreads();

        #pragma unroll
        for (int kk = 0; kk < BK; kk++) {
            float a[8], bb[8];
            *(float4*)(a)      = *(const float4*)&As[kk][tm];
            *(float4*)(a + 4)  = *(const float4*)&As[kk][tm + 4];
            *(float4*)(bb)     = *(const float4*)&Bs[kk][tn];
            *(float4*)(bb + 4) = *(const float4*)&Bs[kk][tn + 4];
            #pragma unroll
            for (int i = 0; i < 8; i++)
                #pragma unroll
                for (int j = 0; j < 8; j++)
                    acc[i][j] = fmaf(a[i], bb[j], acc[i][j]);
        }
        __syncthreads();
    }

    // epilogue: v = acc*scale + bias[row] (+ resid)
    #pragma unroll
    for (int i = 0; i < 8; i++) {
        int row = m0 + tm + i;
        float bia = bias ? bias[row] : 0.f;
        size_t rowbase = (size_t)row * N + n0 + tn;
        #pragma unroll
        for (int jj = 0; jj < 8; jj += 4) {
            float4 v;
            v.x = acc[i][jj + 0] * scale + bia;
            v.y = acc[i][jj + 1] * scale + bia;
            v.z = acc[i][jj + 2] * scale + bia;
            v.w = acc[i][jj + 3] * scale + bia;
            if (resid) {
                float4 r = *(const float4*)(resid + (size_t)b * sR + rowbase + jj);
                v.x += r.x; v.y += r.y; v.z += r.z; v.w += r.w;
            }
            *(float4*)(C + rowbase + jj) = v;
        }
    }
}

// ---------------------------------------------------------------------------
// Launch
// Inputs (metadata order): x, qkv_w, qkv_b, proj_w, proj_b, gn_scale, gn_bias
// ---------------------------------------------------------------------------
extern "C" void kernel_launch(void* const* d_in, const int* in_sizes, int n_in,
                              void* d_out, int out_size)
{
    const float* x        = (const float*)d_in[0];
    const float* qkv_w    = (const float*)d_in[1];
    const float* qkv_b    = (const float*)d_in[2];
    const float* proj_w   = (const float*)d_in[3];
    const float* proj_b   = (const float*)d_in[4];
    const float* gn_scale = (const float*)d_in[5];
    const float* gn_bias  = (const float*)d_in[6];
    float* out = (float*)d_out;

    float *h_, *qkv_, *ctx_, *att_;
    float2* part_;
    cudaGetSymbolAddress((void**)&h_,   g_h);
    cudaGetSymbolAddress((void**)&qkv_, g_qkv);
    cudaGetSymbolAddress((void**)&ctx_, g_ctx);
    cudaGetSymbolAddress((void**)&att_, g_att);
    cudaGetSymbolAddress((void**)&part_, g_part);

    const long sX   = (long)CC * NN;           // per-batch stride of x/h/att/out
    const long sQKV = (long)3 * CC * NN;
    const long sCTX = (long)CC * CC;
    const float qscale = 0.044194173824159216f; // 512^-0.5

    // 1) GroupNorm
    gn_partial_kernel<<<dim3(BB * GG, SLABS), 256>>>(x, part_);
    gn_apply_kernel<<<dim3(BB * GG, SLABS), 256>>>(x, gn_scale, gn_bias, part_, h_);

    // 2) qkv = W @ h + b       [M=1536, N=4096, K=512]
    gemm_kernel<false, false><<<dim3(NN / BN, 3 * CC / BM, BB), 256>>>(
        qkv_w, 0, h_, sX, qkv_, sQKV, 3 * CC, NN, CC,
        qkv_b, nullptr, 0, 1.f);

    // 3) k = softmax(k) over tokens (in place on qkv middle slice)
    softmax_kernel<<<BB * CC, 256>>>(qkv_);

    // 4) ctx[d,e] = sum_n k[d,n] v[e,n]     [M=512, N=512, K=4096]  NT
    gemm_kernel<false, true><<<dim3(CC / BN, CC / BM, BB), 256>>>(
        qkv_ + (size_t)CC * NN, sQKV, qkv_ + (size_t)2 * CC * NN, sQKV,
        ctx_, sCTX, CC, CC, NN,
        nullptr, nullptr, 0, 1.f);

    // 5) att[e,n] = qscale * sum_d ctx[d,e] q[d,n]   [M=512, N=4096, K=512] TN
    gemm_kernel<true, false><<<dim3(NN / BN, CC / BM, BB), 256>>>(
        ctx_, sCTX, qkv_, sQKV, att_, sX, CC, NN, CC,
        nullptr, nullptr, 0, qscale);

    // 6) out = proj_w @ att + proj_b + x   [M=512, N=4096, K=512] NN + residual
    gemm_kernel<false, false><<<dim3(NN / BN, CC / BM, BB), 256>>>(
        proj_w, 0, att_, sX, out, sX, CC, NN, CC,
        proj_b, x, sX, 1.f);
}